// round 8
// baseline (speedup 1.0000x reference)
#include <cuda_runtime.h>
#include <math.h>

#define FULL_MASK 0xffffffffu
#define TWO_PI_F 6.28318530717958647692f

// ---------------- packed f32x2 primitives ----------------
typedef unsigned long long f2;   // two packed fp32 lanes: {lo, hi}

__device__ __forceinline__ f2 f2pack(float a, float b) {
    f2 r; asm("mov.b64 %0, {%1, %2};" : "=l"(r) : "f"(a), "f"(b)); return r;
}
__device__ __forceinline__ void f2unpack(f2 v, float& a, float& b) {
    asm("mov.b64 {%0, %1}, %2;" : "=f"(a), "=f"(b) : "l"(v));
}
__device__ __forceinline__ f2 f2add(f2 a, f2 b) {
    f2 r; asm("add.rn.f32x2 %0, %1, %2;" : "=l"(r) : "l"(a), "l"(b)); return r;
}
__device__ __forceinline__ f2 f2mul(f2 a, f2 b) {
    f2 r; asm("mul.rn.f32x2 %0, %1, %2;" : "=l"(r) : "l"(a), "l"(b)); return r;
}
__device__ __forceinline__ f2 f2fma(f2 a, f2 b, f2 c) {
    f2 r; asm("fma.rn.f32x2 %0, %1, %2, %3;" : "=l"(r) : "l"(a), "l"(b), "l"(c)); return r;
}
__device__ __forceinline__ f2 f2splat(float s) { return f2pack(s, s); }

__device__ __forceinline__ constexpr int brev4c(int p) {
    return ((p & 1) << 3) | ((p & 2) << 1) | ((p & 4) >> 1) | ((p & 8) >> 3);
}

// four-step twiddle table: g_tw512[p*32+lane] = w512^{lane * brev4(p)}
__device__ float2 g_tw512[16 * 32];

__global__ void init_tw_kernel() {
    int e = threadIdx.x;            // 0..511
    int p  = e >> 5;
    int ln = e & 31;
    int k1 = brev4c(p);
    float ang = -(TWO_PI_F / 512.f) * (float)(ln * k1);
    float s, c;
    sincosf(ang, &s, &c);
    g_tw512[p * 32 + ln] = make_float2(c, s);
}

// Per-thread 16-point DIF FFT over 16 register slots (packed: 2 FFTs at once).
// Input slot s = time index; output slot p = bin brev4(p). Compile-time twiddles.
__device__ __forceinline__ void fft16_regs(f2 (&xr)[16], f2 (&xi)[16], f2 NEG)
{
    const float C1 = 0.9238795325f, C2 = 0.7071067812f, C3 = 0.3826834324f;
    {   // span 8, twiddles w16^j
        const float WR[8] = {1.f,  C1,  C2,  C3, 0.f, -C3, -C2, -C1};
        const float WI[8] = {0.f, -C3, -C2, -C1, -1.f, -C1, -C2, -C3};
        #pragma unroll
        for (int j = 0; j < 8; ++j) {
            f2 ur = f2add(xr[j], xr[j+8]),        ui = f2add(xi[j], xi[j+8]);
            f2 vr = f2fma(xr[j+8], NEG, xr[j]),   vi = f2fma(xi[j+8], NEG, xi[j]);
            xr[j] = ur; xi[j] = ui;
            if (j == 0)      { xr[j+8] = vr;  xi[j+8] = vi; }
            else if (j == 4) { xr[j+8] = vi;  xi[j+8] = f2mul(vr, NEG); }     // * -i
            else {
                f2 wr = f2splat(WR[j]), wi = f2splat(WI[j]);
                f2 t1 = f2mul(vi, wi);
                xr[j+8] = f2fma(t1, NEG, f2mul(vr, wr));
                xi[j+8] = f2fma(vi, wr, f2mul(vr, wi));
            }
        }
    }
    {   // span 4, twiddles w8^j
        const float WR[4] = {1.f,  C2, 0.f, -C2};
        const float WI[4] = {0.f, -C2, -1.f, -C2};
        #pragma unroll
        for (int b = 0; b < 16; b += 8)
        #pragma unroll
        for (int j = 0; j < 4; ++j) {
            int p = b + j, q = p + 4;
            f2 ur = f2add(xr[p], xr[q]),        ui = f2add(xi[p], xi[q]);
            f2 vr = f2fma(xr[q], NEG, xr[p]),   vi = f2fma(xi[q], NEG, xi[p]);
            xr[p] = ur; xi[p] = ui;
            if (j == 0)      { xr[q] = vr; xi[q] = vi; }
            else if (j == 2) { xr[q] = vi; xi[q] = f2mul(vr, NEG); }          // * -i
            else {
                f2 wr = f2splat(WR[j]), wi = f2splat(WI[j]);
                f2 t1 = f2mul(vi, wi);
                xr[q] = f2fma(t1, NEG, f2mul(vr, wr));
                xi[q] = f2fma(vi, wr, f2mul(vr, wi));
            }
        }
    }
    // span 2, twiddles {1, -i}
    #pragma unroll
    for (int b = 0; b < 16; b += 4) {
        {
            int p = b, q = b + 2;
            f2 ur = f2add(xr[p], xr[q]),      ui = f2add(xi[p], xi[q]);
            f2 vr = f2fma(xr[q], NEG, xr[p]), vi = f2fma(xi[q], NEG, xi[p]);
            xr[p] = ur; xi[p] = ui; xr[q] = vr; xi[q] = vi;
        }
        {
            int p = b + 1, q = b + 3;
            f2 ur = f2add(xr[p], xr[q]),      ui = f2add(xi[p], xi[q]);
            f2 vr = f2fma(xr[q], NEG, xr[p]), vi = f2fma(xi[q], NEG, xi[p]);
            xr[p] = ur; xi[p] = ui;
            xr[q] = vi; xi[q] = f2mul(vr, NEG);   // * -i
        }
    }
    // span 1
    #pragma unroll
    for (int b = 0; b < 16; b += 2) {
        f2 ur = f2add(xr[b], xr[b+1]),      ui = f2add(xi[b], xi[b+1]);
        f2 vr = f2fma(xr[b+1], NEG, xr[b]), vi = f2fma(xi[b+1], NEG, xi[b]);
        xr[b] = ur; xi[b] = ui; xr[b+1] = vr; xi[b+1] = vi;
    }
}

// Full 512-point packed FFT (two independent FFTs in f2 lanes).
// Output: slot p on lane (=16*par+k1) holds bin k = lane + 32*brev4(p).
// Single-round float4 slab transpose with the n3 radix-2 folded into the read.
__device__ __forceinline__ void fft512C(f2 (&xr)[16], f2 (&xi)[16],
                                        int lane, int par,
                                        ulonglong2* __restrict__ slab,
                                        f2 NEG, f2 SP)
{
    // w32^s tables as compile-time literals (immediate operands, no LDC/reg pinning)
    constexpr float W32R_[16] = {
        1.f, 0.98078528f, 0.92387953f, 0.83146961f, 0.70710678f, 0.55557023f,
        0.38268343f, 0.19509032f, 0.f, -0.19509032f, -0.38268343f, -0.55557023f,
        -0.70710678f, -0.83146961f, -0.92387953f, -0.98078528f };
    constexpr float W32I_[16] = {
        0.f, -0.19509032f, -0.38268343f, -0.55557023f, -0.70710678f, -0.83146961f,
        -0.92387953f, -0.98078528f, -1.f, -0.98078528f, -0.92387953f, -0.83146961f,
        -0.70710678f, -0.55557023f, -0.38268343f, -0.19509032f };

    // pass 1: FFT16 over slots (n1)
    fft16_regs(xr, xi, NEG);

    // four-step twiddle: slot p *= w512^{lane * brev4(p)} (global table, L1-resident)
    #pragma unroll
    for (int p = 1; p < 16; ++p) {
        float2 w = __ldg(&g_tw512[p * 32 + lane]);
        f2 wr = f2splat(w.x), wi = f2splat(w.y);
        f2 t1 = f2mul(xi[p], wi);
        f2 ni = f2fma(xi[p], wr, f2mul(xr[p], wi));
        xr[p] = f2fma(t1, NEG, f2mul(xr[p], wr));
        xi[p] = ni;
    }

    const int wb = (lane & 15) * 33;    // read row base (pad-33 float4 rows)

    // single-round transpose: {xr,xi} as one 16B element; fold n3 radix-2 on read
    __syncwarp();
    #pragma unroll
    for (int p = 0; p < 16; ++p)
        slab[brev4c(p) * 33 + lane] = make_ulonglong2(xr[p], xi[p]);
    __syncwarp();
    #pragma unroll
    for (int s = 0; s < 16; ++s) {
        ulonglong2 y0 = slab[wb + s];
        ulonglong2 y1 = slab[wb + s + 16];
        xr[s] = f2fma((f2)y1.x, SP, (f2)y0.x);   // e (par=0) | y0-y1 (par=1)
        xi[s] = f2fma((f2)y1.y, SP, (f2)y0.y);
    }

    // odd-branch pre-twiddle: par=1 lanes multiply by w32^{n2}; par=0 by 1 (FSEL w/ imm)
    #pragma unroll
    for (int s = 1; s < 16; ++s) {
        float cr = par ? W32R_[s] : 1.f;
        float ci = par ? W32I_[s] : 0.f;
        f2 wr = f2splat(cr), wi = f2splat(ci);
        f2 t1 = f2mul(xi[s], wi);
        f2 ni = f2fma(xi[s], wr, f2mul(xr[s], wi));
        xr[s] = f2fma(t1, NEG, f2mul(xr[s], wr));
        xi[s] = ni;
    }

    // pass 2: FFT16 over n2 -> k2 = 2*brev4(slot) + par
    fft16_regs(xr, xi, NEG);
}

// out[b] = Im( sum_f Z[f]^2 * conj(T[f]) ) / (2*D), Z = FFT(h+ir), T = FFT(t).
// Packed per row: lo = Z-FFT, hi = T-FFT. Independent rows -> full pipelining.
// occ 5 blocks/SM (20 warps): forces regs <= 102 for latency tolerance.
__global__ void __launch_bounds__(128, 5)
hole_kernel(const float* __restrict__ h, const float* __restrict__ r,
            const float* __restrict__ t, float* __restrict__ out, int nrows)
{
    const int lane = threadIdx.x & 31;
    const int wid  = threadIdx.x >> 5;
    const int warp = blockIdx.x * 4 + wid;
    const int nw   = gridDim.x * 4;
    const int par  = lane >> 4;

    __shared__ ulonglong2 slab_s[4][16 * 33];   // 8.25 KB/warp float4 slab
    ulonglong2* __restrict__ slab = slab_s[wid];

    const f2 NEG = f2splat(-1.f);
    const f2 SP  = f2splat(par ? -1.f : 1.f);

    for (int row = warp; row < nrows; row += nw) {
        size_t base = (size_t)row * 512 + (size_t)lane;
        const float* hp = h + base;
        const float* rp = r + base;
        const float* tp = t + base;

        // coalesced loads; lo = Z input (h + i r), hi = T input (t + i 0)
        f2 xr[16], xi[16];
        #pragma unroll
        for (int s = 0; s < 16; ++s) {
            float hv = hp[32 * s];
            float tv = tp[32 * s];
            float rv = rp[32 * s];
            xr[s] = f2pack(hv, tv);
            xi[s] = f2pack(rv, 0.f);
        }

        fft512C(xr, xi, lane, par, slab, NEG, SP);

        // acc = sum over this lane's 16 bins of Im(Z^2 * conj(T))
        float acc = 0.f;
        #pragma unroll
        for (int s = 0; s < 16; ++s) {
            float a, tr, b, ti;
            f2unpack(xr[s], a, tr);    // lo = Re Z, hi = Re T
            f2unpack(xi[s], b, ti);    // lo = Im Z, hi = Im T
            float im2 = 2.f * a * b;               // Im(Z^2)
            float re2 = a * a - b * b;             // Re(Z^2)
            acc = fmaf(im2, tr, acc);
            acc = fmaf(-re2, ti, acc);
        }
        #pragma unroll
        for (int o = 16; o; o >>= 1)
            acc += __shfl_xor_sync(FULL_MASK, acc, o);

        if (lane == 0) out[row] = acc * (1.f / 1024.f);   // 1/(2*D)
    }
}

extern "C" void kernel_launch(void* const* d_in, const int* in_sizes, int n_in,
                              void* d_out, int out_size)
{
    const float* h = (const float*)d_in[0];
    const float* r = (const float*)d_in[1];
    const float* t = (const float*)d_in[2];
    float* out = (float*)d_out;

    int nrows = in_sizes[0] / 512;      // 131072

    init_tw_kernel<<<1, 512>>>();       // idempotent, graph-capturable
    hole_kernel<<<4096, 128>>>(h, r, t, out, nrows);   // 16384 warps -> 8 rows/warp
}

// round 9
// speedup vs baseline: 1.0799x; 1.0799x over previous
#include <cuda_runtime.h>
#include <math.h>

#define FULL_MASK 0xffffffffu
#define TWO_PI_F 6.28318530717958647692f

// ---------------- packed f32x2 primitives ----------------
typedef unsigned long long f2;   // two packed fp32 lanes: {lo, hi}

__device__ __forceinline__ f2 f2pack(float a, float b) {
    f2 r; asm("mov.b64 %0, {%1, %2};" : "=l"(r) : "f"(a), "f"(b)); return r;
}
__device__ __forceinline__ void f2unpack(f2 v, float& a, float& b) {
    asm("mov.b64 {%0, %1}, %2;" : "=f"(a), "=f"(b) : "l"(v));
}
__device__ __forceinline__ f2 f2add(f2 a, f2 b) {
    f2 r; asm("add.rn.f32x2 %0, %1, %2;" : "=l"(r) : "l"(a), "l"(b)); return r;
}
__device__ __forceinline__ f2 f2mul(f2 a, f2 b) {
    f2 r; asm("mul.rn.f32x2 %0, %1, %2;" : "=l"(r) : "l"(a), "l"(b)); return r;
}
__device__ __forceinline__ f2 f2fma(f2 a, f2 b, f2 c) {
    f2 r; asm("fma.rn.f32x2 %0, %1, %2, %3;" : "=l"(r) : "l"(a), "l"(b), "l"(c)); return r;
}
__device__ __forceinline__ f2 f2splat(float s) { return f2pack(s, s); }

__device__ __forceinline__ constexpr int brev4c(int p) {
    return ((p & 1) << 3) | ((p & 2) << 1) | ((p & 4) >> 1) | ((p & 8) >> 3);
}

// Per-thread 16-point DIF FFT over 16 register slots (packed: 2 FFTs at once).
// Input slot s = time index; output slot p = bin brev4(p). Compile-time twiddles.
__device__ __forceinline__ void fft16_regs(f2 (&xr)[16], f2 (&xi)[16], f2 NEG)
{
    const float C1 = 0.9238795325f, C2 = 0.7071067812f, C3 = 0.3826834324f;
    {   // span 8, twiddles w16^j
        const float WR[8] = {1.f,  C1,  C2,  C3, 0.f, -C3, -C2, -C1};
        const float WI[8] = {0.f, -C3, -C2, -C1, -1.f, -C1, -C2, -C3};
        #pragma unroll
        for (int j = 0; j < 8; ++j) {
            f2 ur = f2add(xr[j], xr[j+8]),        ui = f2add(xi[j], xi[j+8]);
            f2 vr = f2fma(xr[j+8], NEG, xr[j]),   vi = f2fma(xi[j+8], NEG, xi[j]);
            xr[j] = ur; xi[j] = ui;
            if (j == 0)      { xr[j+8] = vr;  xi[j+8] = vi; }
            else if (j == 4) { xr[j+8] = vi;  xi[j+8] = f2mul(vr, NEG); }     // * -i
            else {
                f2 wr = f2splat(WR[j]), wi = f2splat(WI[j]);
                f2 t1 = f2mul(vi, wi);
                xr[j+8] = f2fma(t1, NEG, f2mul(vr, wr));
                xi[j+8] = f2fma(vi, wr, f2mul(vr, wi));
            }
        }
    }
    {   // span 4, twiddles w8^j
        const float WR[4] = {1.f,  C2, 0.f, -C2};
        const float WI[4] = {0.f, -C2, -1.f, -C2};
        #pragma unroll
        for (int b = 0; b < 16; b += 8)
        #pragma unroll
        for (int j = 0; j < 4; ++j) {
            int p = b + j, q = p + 4;
            f2 ur = f2add(xr[p], xr[q]),        ui = f2add(xi[p], xi[q]);
            f2 vr = f2fma(xr[q], NEG, xr[p]),   vi = f2fma(xi[q], NEG, xi[p]);
            xr[p] = ur; xi[p] = ui;
            if (j == 0)      { xr[q] = vr; xi[q] = vi; }
            else if (j == 2) { xr[q] = vi; xi[q] = f2mul(vr, NEG); }          // * -i
            else {
                f2 wr = f2splat(WR[j]), wi = f2splat(WI[j]);
                f2 t1 = f2mul(vi, wi);
                xr[q] = f2fma(t1, NEG, f2mul(vr, wr));
                xi[q] = f2fma(vi, wr, f2mul(vr, wi));
            }
        }
    }
    // span 2, twiddles {1, -i}
    #pragma unroll
    for (int b = 0; b < 16; b += 4) {
        {
            int p = b, q = b + 2;
            f2 ur = f2add(xr[p], xr[q]),      ui = f2add(xi[p], xi[q]);
            f2 vr = f2fma(xr[q], NEG, xr[p]), vi = f2fma(xi[q], NEG, xi[p]);
            xr[p] = ur; xi[p] = ui; xr[q] = vr; xi[q] = vi;
        }
        {
            int p = b + 1, q = b + 3;
            f2 ur = f2add(xr[p], xr[q]),      ui = f2add(xi[p], xi[q]);
            f2 vr = f2fma(xr[q], NEG, xr[p]), vi = f2fma(xi[q], NEG, xi[p]);
            xr[p] = ur; xi[p] = ui;
            xr[q] = vi; xi[q] = f2mul(vr, NEG);   // * -i
        }
    }
    // span 1
    #pragma unroll
    for (int b = 0; b < 16; b += 2) {
        f2 ur = f2add(xr[b], xr[b+1]),      ui = f2add(xi[b], xi[b+1]);
        f2 vr = f2fma(xr[b+1], NEG, xr[b]), vi = f2fma(xi[b+1], NEG, xi[b]);
        xr[b] = ur; xi[b] = ui; xr[b+1] = vr; xi[b+1] = vi;
    }
}

// Full 512-point packed FFT (two independent FFTs in f2 lanes).
// Output: slot p on lane (=16*par+k1) holds bin k = lane + 32*brev4(p).
// Single-round float4 slab transpose with the n3 radix-2 folded into the read.
__device__ __forceinline__ void fft512C(f2 (&xr)[16], f2 (&xi)[16],
                                        int lane, int par,
                                        ulonglong2* __restrict__ slab,
                                        const float2* __restrict__ tw512,
                                        f2 NEG, f2 SP)
{
    // w32^s tables as compile-time literals
    constexpr float W32R_[16] = {
        1.f, 0.98078528f, 0.92387953f, 0.83146961f, 0.70710678f, 0.55557023f,
        0.38268343f, 0.19509032f, 0.f, -0.19509032f, -0.38268343f, -0.55557023f,
        -0.70710678f, -0.83146961f, -0.92387953f, -0.98078528f };
    constexpr float W32I_[16] = {
        0.f, -0.19509032f, -0.38268343f, -0.55557023f, -0.70710678f, -0.83146961f,
        -0.92387953f, -0.98078528f, -1.f, -0.98078528f, -0.92387953f, -0.83146961f,
        -0.70710678f, -0.55557023f, -0.38268343f, -0.19509032f };

    // pass 1: FFT16 over slots (n1)
    fft16_regs(xr, xi, NEG);

    // four-step twiddle: slot p *= w512^{lane * brev4(p)}  (per-block smem table,
    // LDS on the shared port — keeps the global LSU path clear for streaming LDGs)
    #pragma unroll
    for (int p = 1; p < 16; ++p) {
        float2 w = tw512[p * 32 + lane];
        f2 wr = f2splat(w.x), wi = f2splat(w.y);
        f2 t1 = f2mul(xi[p], wi);
        f2 ni = f2fma(xi[p], wr, f2mul(xr[p], wi));
        xr[p] = f2fma(t1, NEG, f2mul(xr[p], wr));
        xi[p] = ni;
    }

    const int wb = (lane & 15) * 33;    // read row base (pad-33 float4 rows)

    // single-round transpose: {xr,xi} as one 16B element; fold n3 radix-2 on read
    __syncwarp();
    #pragma unroll
    for (int p = 0; p < 16; ++p)
        slab[brev4c(p) * 33 + lane] = make_ulonglong2(xr[p], xi[p]);
    __syncwarp();
    #pragma unroll
    for (int s = 0; s < 16; ++s) {
        ulonglong2 y0 = slab[wb + s];
        ulonglong2 y1 = slab[wb + s + 16];
        xr[s] = f2fma((f2)y1.x, SP, (f2)y0.x);   // e (par=0) | y0-y1 (par=1)
        xi[s] = f2fma((f2)y1.y, SP, (f2)y0.y);
    }

    // odd-branch pre-twiddle: par=1 lanes multiply by w32^{n2}; par=0 by 1 (FSEL w/ imm)
    #pragma unroll
    for (int s = 1; s < 16; ++s) {
        float cr = par ? W32R_[s] : 1.f;
        float ci = par ? W32I_[s] : 0.f;
        f2 wr = f2splat(cr), wi = f2splat(ci);
        f2 t1 = f2mul(xi[s], wi);
        f2 ni = f2fma(xi[s], wr, f2mul(xr[s], wi));
        xr[s] = f2fma(t1, NEG, f2mul(xr[s], wr));
        xi[s] = ni;
    }

    // pass 2: FFT16 over n2 -> k2 = 2*brev4(slot) + par
    fft16_regs(xr, xi, NEG);
}

// out[b] = Im( sum_f Z[f]^2 * conj(T[f]) ) / (2*D), Z = FFT(h+ir), T = FFT(t).
// Packed per row: lo = Z-FFT, hi = T-FFT. Independent rows -> full pipelining.
__global__ void __launch_bounds__(128, 4)
hole_kernel(const float* __restrict__ h, const float* __restrict__ r,
            const float* __restrict__ t, float* __restrict__ out, int nrows)
{
    const int lane = threadIdx.x & 31;
    const int wid  = threadIdx.x >> 5;
    const int warp = blockIdx.x * 4 + wid;
    const int nw   = gridDim.x * 4;
    const int par  = lane >> 4;

    __shared__ ulonglong2 slab_s[4][16 * 33];   // 8.25 KB/warp float4 slab
    __shared__ float2 tw512[16 * 32];           // 4 KB four-step twiddle table
    ulonglong2* __restrict__ slab = slab_s[wid];

    // per-block twiddle init: tw512[p*32+ln] = w512^{ln * brev4(p)}
    for (int e = threadIdx.x; e < 512; e += 128) {
        int p  = e >> 5;
        int ln = e & 31;
        float ang = -(TWO_PI_F / 512.f) * (float)(ln * brev4c(p));
        float s, c;
        sincosf(ang, &s, &c);
        tw512[e] = make_float2(c, s);
    }
    __syncthreads();

    const f2 NEG = f2splat(-1.f);
    const f2 SP  = f2splat(par ? -1.f : 1.f);

    for (int row = warp; row < nrows; row += nw) {
        size_t base = (size_t)row * 512 + (size_t)lane;
        const float* hp = h + base;
        const float* rp = r + base;
        const float* tp = t + base;

        // coalesced loads; lo = Z input (h + i r), hi = T input (t + i 0)
        f2 xr[16], xi[16];
        #pragma unroll
        for (int s = 0; s < 16; ++s) {
            float hv = hp[32 * s];
            float tv = tp[32 * s];
            float rv = rp[32 * s];
            xr[s] = f2pack(hv, tv);
            xi[s] = f2pack(rv, 0.f);
        }

        fft512C(xr, xi, lane, par, slab, tw512, NEG, SP);

        // reduction with 4 independent accumulator chains (breaks the 32-FFMA
        // dependent chain; combine at the end)
        float a0 = 0.f, a1 = 0.f, a2s = 0.f, a3 = 0.f;
        #pragma unroll
        for (int s = 0; s < 16; s += 4) {
            #pragma unroll
            for (int j = 0; j < 4; ++j) {
                float a, tr, b, ti;
                f2unpack(xr[s + j], a, tr);    // lo = Re Z, hi = Re T
                f2unpack(xi[s + j], b, ti);    // lo = Im Z, hi = Im T
                float im2 = 2.f * a * b;               // Im(Z^2)
                float re2 = a * a - b * b;             // Re(Z^2)
                if (j == 0)      { a0  = fmaf(im2, tr, a0);  a0  = fmaf(-re2, ti, a0); }
                else if (j == 1) { a1  = fmaf(im2, tr, a1);  a1  = fmaf(-re2, ti, a1); }
                else if (j == 2) { a2s = fmaf(im2, tr, a2s); a2s = fmaf(-re2, ti, a2s); }
                else             { a3  = fmaf(im2, tr, a3);  a3  = fmaf(-re2, ti, a3); }
            }
        }
        float acc = (a0 + a1) + (a2s + a3);

        #pragma unroll
        for (int o = 16; o; o >>= 1)
            acc += __shfl_xor_sync(FULL_MASK, acc, o);

        if (lane == 0) out[row] = acc * (1.f / 1024.f);   // 1/(2*D)
    }
}

extern "C" void kernel_launch(void* const* d_in, const int* in_sizes, int n_in,
                              void* d_out, int out_size)
{
    const float* h = (const float*)d_in[0];
    const float* r = (const float*)d_in[1];
    const float* t = (const float*)d_in[2];
    float* out = (float*)d_out;

    int nrows = in_sizes[0] / 512;      // 131072

    hole_kernel<<<4096, 128>>>(h, r, t, out, nrows);   // 16384 warps -> 8 rows/warp
}

// round 10
// speedup vs baseline: 1.1327x; 1.0489x over previous
#include <cuda_runtime.h>
#include <math.h>

#define FULL_MASK 0xffffffffu
#define TWO_PI_F 6.28318530717958647692f

// ---------------- packed f32x2 primitives ----------------
typedef unsigned long long f2;   // two packed fp32 lanes: {lo, hi}

__device__ __forceinline__ f2 f2pack(float a, float b) {
    f2 r; asm("mov.b64 %0, {%1, %2};" : "=l"(r) : "f"(a), "f"(b)); return r;
}
__device__ __forceinline__ void f2unpack(f2 v, float& a, float& b) {
    asm("mov.b64 {%0, %1}, %2;" : "=f"(a), "=f"(b) : "l"(v));
}
__device__ __forceinline__ f2 f2add(f2 a, f2 b) {
    f2 r; asm("add.rn.f32x2 %0, %1, %2;" : "=l"(r) : "l"(a), "l"(b)); return r;
}
__device__ __forceinline__ f2 f2mul(f2 a, f2 b) {
    f2 r; asm("mul.rn.f32x2 %0, %1, %2;" : "=l"(r) : "l"(a), "l"(b)); return r;
}
__device__ __forceinline__ f2 f2fma(f2 a, f2 b, f2 c) {
    f2 r; asm("fma.rn.f32x2 %0, %1, %2, %3;" : "=l"(r) : "l"(a), "l"(b), "l"(c)); return r;
}
__device__ __forceinline__ f2 f2splat(float s) { return f2pack(s, s); }

// digit-swap permutation for radix-4 FFT16: p = 4s+q  ->  k = 4q+s
__device__ __forceinline__ constexpr int dig4c(int p) {
    return ((p & 3) << 2) | (p >> 2);
}

// four-step twiddle table: g_tw512[p*32+lane] = w512^{lane * dig4(p)}
__device__ float2 g_tw512[16 * 32];

__global__ void init_tw_kernel() {
    int e = threadIdx.x;            // 0..511
    int p  = e >> 5;
    int ln = e & 31;
    int k1 = dig4c(p);
    float ang = -(TWO_PI_F / 512.f) * (float)(ln * k1);
    float s, c;
    sincosf(ang, &s, &c);
    g_tw512[p * 32 + ln] = make_float2(c, s);
}

// complex multiply helper: (xr,xi) *= (wr,wi), compile-time w; 5 packed ops
#define CMUL_CONST(XR, XI, WR, WI, NEG) do {                         \
    f2 _wr = f2splat(WR), _wi = f2splat(WI);                         \
    f2 _t1 = f2mul(XI, _wi);                                         \
    f2 _ni = f2fma(XI, _wr, f2mul(XR, _wi));                         \
    XR = f2fma(_t1, NEG, f2mul(XR, _wr));                            \
    XI = _ni;                                                        \
} while (0)

// Per-thread radix-4 16-point DIF FFT over 16 register slots (packed: 2 FFTs).
// Input slot s = time index n. Output slot p holds bin dig4(p) = 4(p&3)+(p>>2).
__device__ __forceinline__ void fft16_r4(f2 (&xr)[16], f2 (&xi)[16], f2 NEG)
{
    const float C1 = 0.9238795325f, C2 = 0.7071067812f, C3 = 0.3826834324f;

    // ---- stage 1: radix-4 over stride-4 groups n=0..3, with w16^{n*s} twiddles
    #pragma unroll
    for (int n = 0; n < 4; ++n) {
        f2 t0r = f2add(xr[n],     xr[n + 8]), t0i = f2add(xi[n],     xi[n + 8]);
        f2 t1r = f2fma(xr[n + 8], NEG, xr[n]), t1i = f2fma(xi[n + 8], NEG, xi[n]);
        f2 t2r = f2add(xr[n + 4], xr[n + 12]), t2i = f2add(xi[n + 4], xi[n + 12]);
        f2 t3r = f2fma(xr[n + 12], NEG, xr[n + 4]), t3i = f2fma(xi[n + 12], NEG, xi[n + 4]);

        // u0 = t0+t2 -> slot n (s=0, twiddle 1)
        xr[n] = f2add(t0r, t2r);
        xi[n] = f2add(t0i, t2i);
        // u1 = t1 - i t3 -> slot 4+n, * w16^{n}
        f2 u1r = f2add(t1r, t3i);
        f2 u1i = f2fma(t3r, NEG, t1i);
        // u2 = t0 - t2 -> slot 8+n, * w16^{2n}
        f2 u2r = f2fma(t2r, NEG, t0r);
        f2 u2i = f2fma(t2i, NEG, t0i);
        // u3 = t1 + i t3 -> slot 12+n, * w16^{3n}
        f2 u3r = f2fma(t3i, NEG, t1r);
        f2 u3i = f2add(t1i, t3r);

        if (n == 1) {
            CMUL_CONST(u1r, u1i,  C1, -C3, NEG);   // w16^1
            CMUL_CONST(u2r, u2i,  C2, -C2, NEG);   // w16^2
            CMUL_CONST(u3r, u3i,  C3, -C1, NEG);   // w16^3
        } else if (n == 2) {
            CMUL_CONST(u1r, u1i,  C2, -C2, NEG);   // w16^2
            { f2 tr = u2r; u2r = u2i; u2i = f2mul(tr, NEG); }   // w16^4 = -i
            CMUL_CONST(u3r, u3i, -C2, -C2, NEG);   // w16^6
        } else if (n == 3) {
            CMUL_CONST(u1r, u1i,  C3, -C1, NEG);   // w16^3
            CMUL_CONST(u2r, u2i, -C2, -C2, NEG);   // w16^6
            CMUL_CONST(u3r, u3i, -C1,  C3, NEG);   // w16^9
        }
        xr[n + 4] = u1r;  xi[n + 4] = u1i;
        xr[n + 8] = u2r;  xi[n + 8] = u2i;
        xr[n + 12] = u3r; xi[n + 12] = u3i;
    }

    // ---- stage 2: radix-4 within each 4-slot block (no twiddles)
    #pragma unroll
    for (int s = 0; s < 4; ++s) {
        int b = 4 * s;
        f2 t0r = f2add(xr[b],     xr[b + 2]), t0i = f2add(xi[b],     xi[b + 2]);
        f2 t1r = f2fma(xr[b + 2], NEG, xr[b]), t1i = f2fma(xi[b + 2], NEG, xi[b]);
        f2 t2r = f2add(xr[b + 1], xr[b + 3]), t2i = f2add(xi[b + 1], xi[b + 3]);
        f2 t3r = f2fma(xr[b + 3], NEG, xr[b + 1]), t3i = f2fma(xi[b + 3], NEG, xi[b + 1]);

        xr[b]     = f2add(t0r, t2r);              xi[b]     = f2add(t0i, t2i);
        xr[b + 1] = f2add(t1r, t3i);              xi[b + 1] = f2fma(t3r, NEG, t1i);   // q=1: t1 - i t3
        xr[b + 2] = f2fma(t2r, NEG, t0r);         xi[b + 2] = f2fma(t2i, NEG, t0i);   // q=2
        xr[b + 3] = f2fma(t3i, NEG, t1r);         xi[b + 3] = f2add(t1i, t3r);        // q=3: t1 + i t3
    }
}

// Full 512-point packed FFT (two independent FFTs in f2 lanes).
// Output: slot p on lane (=16*par+k1) holds bin k = lane + 32*dig4(p).
// Single-round float4 slab transpose with the n3 radix-2 AND the w32^{n2}
// odd-branch twiddle both folded into the read.
__device__ __forceinline__ void fft512D(f2 (&xr)[16], f2 (&xi)[16],
                                        int lane, int par,
                                        ulonglong2* __restrict__ slab,
                                        f2 NEG, f2 SP)
{
    // w32^s tables as compile-time literals
    constexpr float W32R_[16] = {
        1.f, 0.98078528f, 0.92387953f, 0.83146961f, 0.70710678f, 0.55557023f,
        0.38268343f, 0.19509032f, 0.f, -0.19509032f, -0.38268343f, -0.55557023f,
        -0.70710678f, -0.83146961f, -0.92387953f, -0.98078528f };
    constexpr float W32I_[16] = {
        0.f, -0.19509032f, -0.38268343f, -0.55557023f, -0.70710678f, -0.83146961f,
        -0.92387953f, -0.98078528f, -1.f, -0.98078528f, -0.92387953f, -0.83146961f,
        -0.70710678f, -0.55557023f, -0.38268343f, -0.19509032f };

    // pass 1: FFT16 over slots (n1)
    fft16_r4(xr, xi, NEG);

    // four-step twiddle: slot p *= w512^{lane * dig4(p)} (global table, L1-resident)
    #pragma unroll
    for (int p = 1; p < 16; ++p) {
        float2 w = __ldg(&g_tw512[p * 32 + lane]);
        f2 wr = f2splat(w.x), wi = f2splat(w.y);
        f2 t1 = f2mul(xi[p], wi);
        f2 ni = f2fma(xi[p], wr, f2mul(xr[p], wi));
        xr[p] = f2fma(t1, NEG, f2mul(xr[p], wr));
        xi[p] = ni;
    }

    const int wb = (lane & 15) * 33;    // read row base (pad-33 float4 rows)

    // single-round transpose: {xr,xi} as one 16B element; fold n3 radix-2 and
    // odd-branch w32^{n2} twiddle into the read:
    //   par=0: x = y0 + y1
    //   par=1: x = (y0 - y1) * w32^{s}
    __syncwarp();
    #pragma unroll
    for (int p = 0; p < 16; ++p)
        slab[dig4c(p) * 33 + lane] = make_ulonglong2(xr[p], xi[p]);
    __syncwarp();
    #pragma unroll
    for (int s = 0; s < 16; ++s) {
        ulonglong2 y0 = slab[wb + s];
        ulonglong2 y1 = slab[wb + s + 16];
        f2 dr = f2fma((f2)y1.x, SP, (f2)y0.x);   // y0r +/- y1r
        f2 di = f2fma((f2)y1.y, SP, (f2)y0.y);
        if (s == 0) {
            xr[0] = dr; xi[0] = di;
        } else {
            float cr  = par ? W32R_[s] : 1.f;    // FSEL (alu pipe)
            float ci  = par ? W32I_[s] : 0.f;
            float cin = par ? -W32I_[s] : 0.f;
            f2 wr = f2splat(cr), wi = f2splat(ci), win = f2splat(cin);
            xr[s] = f2fma(di, win, f2mul(dr, wr));
            xi[s] = f2fma(di, wr,  f2mul(dr, wi));
        }
    }

    // pass 2: FFT16 over n2 -> k2 = 2*dig4(slot) + par
    fft16_r4(xr, xi, NEG);
}

// out[b] = Im( sum_f Z[f]^2 * conj(T[f]) ) / (2*D), Z = FFT(h+ir), T = FFT(t).
// Packed per row: lo = Z-FFT, hi = T-FFT. Independent rows -> full pipelining.
__global__ void __launch_bounds__(128, 4)
hole_kernel(const float* __restrict__ h, const float* __restrict__ r,
            const float* __restrict__ t, float* __restrict__ out, int nrows)
{
    const int lane = threadIdx.x & 31;
    const int wid  = threadIdx.x >> 5;
    const int warp = blockIdx.x * 4 + wid;
    const int nw   = gridDim.x * 4;
    const int par  = lane >> 4;

    __shared__ ulonglong2 slab_s[4][16 * 33];   // 8.25 KB/warp float4 slab
    ulonglong2* __restrict__ slab = slab_s[wid];

    const f2 NEG = f2splat(-1.f);
    const f2 SP  = f2splat(par ? -1.f : 1.f);

    for (int row = warp; row < nrows; row += nw) {
        size_t base = (size_t)row * 512 + (size_t)lane;
        const float* hp = h + base;
        const float* rp = r + base;
        const float* tp = t + base;

        // coalesced loads; lo = Z input (h + i r), hi = T input (t + i 0)
        f2 xr[16], xi[16];
        #pragma unroll
        for (int s = 0; s < 16; ++s) {
            float hv = hp[32 * s];
            float tv = tp[32 * s];
            float rv = rp[32 * s];
            xr[s] = f2pack(hv, tv);
            xi[s] = f2pack(rv, 0.f);
        }

        fft512D(xr, xi, lane, par, slab, NEG, SP);

        // acc = sum over this lane's 16 bins of Im(Z^2 * conj(T))
        float acc = 0.f;
        #pragma unroll
        for (int s = 0; s < 16; ++s) {
            float a, tr, b, ti;
            f2unpack(xr[s], a, tr);    // lo = Re Z, hi = Re T
            f2unpack(xi[s], b, ti);    // lo = Im Z, hi = Im T
            float im2 = 2.f * a * b;               // Im(Z^2)
            float re2 = a * a - b * b;             // Re(Z^2)
            acc = fmaf(im2, tr, acc);
            acc = fmaf(-re2, ti, acc);
        }
        #pragma unroll
        for (int o = 16; o; o >>= 1)
            acc += __shfl_xor_sync(FULL_MASK, acc, o);

        if (lane == 0) out[row] = acc * (1.f / 1024.f);   // 1/(2*D)
    }
}

extern "C" void kernel_launch(void* const* d_in, const int* in_sizes, int n_in,
                              void* d_out, int out_size)
{
    const float* h = (const float*)d_in[0];
    const float* r = (const float*)d_in[1];
    const float* t = (const float*)d_in[2];
    float* out = (float*)d_out;

    int nrows = in_sizes[0] / 512;      // 131072

    init_tw_kernel<<<1, 512>>>();       // idempotent, graph-capturable
    hole_kernel<<<4096, 128>>>(h, r, t, out, nrows);   // 16384 warps -> 8 rows/warp
}